// round 1
// baseline (speedup 1.0000x reference)
#include <cuda_runtime.h>
#include <cuda_bf16.h>
#include <math.h>

// Problem constants (fixed shapes from reference)
#define B_ 32
#define C_ 6
#define T_ 64
#define K_ 8
#define N_ 128
#define S_ 32
#define P_ 64
#define NSEG (K_ * (N_ - 1))   // 1016
#define NCL  (S_ * P_)         // 2048
#define EPS_ 1e-6f
#define THRESH_ 0.5f

#define LANES 8                 // lanes per point
#define PTS_PER_BLOCK 16
#define THREADS (LANES * PTS_PER_BLOCK)   // 128
#define CHUNKS (T_ / PTS_PER_BLOCK)       // 4

__global__ void offroad_init_kernel(float* out) {
    int i = threadIdx.x;
    if (i < B_ * C_) out[i] = 0.0f;
}

__global__ __launch_bounds__(THREADS)
void offroad_kernel(const float* __restrict__ points,
                    const float* __restrict__ road_boundary,
                    const float* __restrict__ centerlines,
                    float* __restrict__ out) {
    __shared__ float4 sSeg[NSEG];   // ax, ay, dx, dy
    __shared__ float  sInv[NSEG];   // 1/(|d|^2 + eps)
    __shared__ float2 sCl[NCL];
    __shared__ float  sVal[PTS_PER_BLOCK];

    const int bid = blockIdx.x;
    const int chunk = bid % CHUNKS;
    const int c = (bid / CHUNKS) % C_;
    const int b = bid / (CHUNKS * C_);
    const int tid = threadIdx.x;

    // ---- Fill shared: segments (a, d, inv) ----
    {
        const float2* rb = (const float2*)(road_boundary) + (size_t)b * K_ * N_;
        #pragma unroll
        for (int s = tid; s < NSEG; s += THREADS) {
            int k = s / (N_ - 1);
            int j = s - k * (N_ - 1);
            float2 a  = rb[k * N_ + j];
            float2 bp = rb[k * N_ + j + 1];
            float dx = bp.x - a.x;
            float dy = bp.y - a.y;
            sSeg[s] = make_float4(a.x, a.y, dx, dy);
            sInv[s] = 1.0f / (dx * dx + dy * dy + EPS_);
        }
    }
    // ---- Fill shared: centerlines ----
    {
        const float4* clg = (const float4*)(centerlines + (size_t)b * NCL * 2);
        #pragma unroll
        for (int i = tid; i < NCL / 2; i += THREADS) {
            float4 v = clg[i];
            sCl[2 * i]     = make_float2(v.x, v.y);
            sCl[2 * i + 1] = make_float2(v.z, v.w);
        }
    }
    __syncthreads();

    const int g = tid >> 3;      // point group within block
    const int l = tid & 7;       // lane within group
    const int t = chunk * PTS_PER_BLOCK + g;

    const float2 p = ((const float2*)points)[((size_t)b * C_ + c) * T_ + t];
    const float px = p.x, py = p.y;

    // ---- Phase A: argmin over centerline candidates ----
    float bd2 = 3.4e38f;
    int bidx = 0x7fffffff;
    #pragma unroll 4
    for (int i = l; i < NCL; i += LANES) {
        float2 q = sCl[i];
        float ddx = px - q.x;
        float ddy = py - q.y;
        float d2 = fmaf(ddx, ddx, ddy * ddy);
        if (d2 < bd2) { bd2 = d2; bidx = i; }
    }
    #pragma unroll
    for (int off = 4; off; off >>= 1) {
        float od2 = __shfl_xor_sync(0xffffffffu, bd2, off);
        int   oix = __shfl_xor_sync(0xffffffffu, bidx, off);
        if (od2 < bd2 || (od2 == bd2 && oix < bidx)) { bd2 = od2; bidx = oix; }
    }
    const float2 q = sCl[bidx];          // broadcast read (all 8 lanes same idx)
    const float dax = q.x - px;
    const float day = q.y - py;

    // ---- Phase B: fused min-distance + intersection over segments ----
    float mind2 = 3.4e38f;
    unsigned hit = 0u;
    #pragma unroll 4
    for (int s = l; s < NSEG; s += LANES) {
        float4 sg = sSeg[s];
        float inv = sInv[s];
        float v1x = px - sg.x;
        float v1y = py - sg.y;
        // point-to-segment distance
        float dt = fmaf(v1x, sg.z, v1y * sg.w);
        float proj = fminf(fmaxf(dt * inv, 0.0f), 1.0f);
        float ex = fmaf(sg.z, proj, -v1x);
        float ey = fmaf(sg.w, proj, -v1y);
        float d2 = fmaf(ex, ex, ey * ey);
        mind2 = fminf(mind2, d2);
        // intersection of (p -> closest_cl) with segment; dp == v1
        float w  = fmaf(dax, sg.w, -(day * sg.z)) + EPS_;   // cross(da,db)+eps
        float c1 = fmaf(dax, v1y, -(day * v1x));            // cross(da,dp)
        float c2 = fmaf(sg.z, v1y, -(sg.w * v1x));          // cross(db,dp)
        // t=c1/w in [0,1] && u=c2/w in [0,1], division-free
        unsigned h = (c1 * w >= 0.0f) & (fabsf(c1) <= fabsf(w)) &
                     (c2 * w >= 0.0f) & (fabsf(c2) <= fabsf(w));
        hit |= h;
    }
    #pragma unroll
    for (int off = 4; off; off >>= 1) {
        mind2 = fminf(mind2, __shfl_xor_sync(0xffffffffu, mind2, off));
        hit  |= __shfl_xor_sync(0xffffffffu, hit, off);
    }

    if (l == 0) {
        float md = sqrtf(mind2);
        if (!hit) md = -md;                 // inside -> negate
        sVal[g] = fmaxf(md + THRESH_, 0.0f);
    }
    __syncthreads();

    if (tid == 0) {
        float s = 0.0f;
        #pragma unroll
        for (int i = 0; i < PTS_PER_BLOCK; i++) s += sVal[i];
        atomicAdd(&out[b * C_ + c], s);
    }
}

extern "C" void kernel_launch(void* const* d_in, const int* in_sizes, int n_in,
                              void* d_out, int out_size) {
    const float* points       = (const float*)d_in[0];
    const float* road_bound   = (const float*)d_in[1];
    const float* centerlines  = (const float*)d_in[2];
    float* out = (float*)d_out;
    (void)in_sizes; (void)n_in; (void)out_size;

    offroad_init_kernel<<<1, 256>>>(out);
    offroad_kernel<<<B_ * C_ * CHUNKS, THREADS>>>(points, road_bound, centerlines, out);
}

// round 2
// speedup vs baseline: 1.1592x; 1.1592x over previous
#include <cuda_runtime.h>
#include <cuda_bf16.h>
#include <math.h>

// Fixed shapes
#define B_ 32
#define C_ 6
#define T_ 64
#define K_ 8
#define N_ 128
#define NSEG (K_ * (N_ - 1))   // 1016
#define NSEGP 1024             // padded with inert dummies
#define NCL 2048
#define EPS_ 1e-6f
#define THRESH_ 0.5f

#define L 16                   // lanes per point-group
#define M 4                    // points per thread
#define THREADS 128
#define GROUPS (THREADS / L)   // 8
#define PTS_BLK (GROUPS * M)   // 32
// grid = B*C*(T/PTS_BLK) = 32*6*2 = 384

__global__ void offroad_init_kernel(float* out) {
    int i = threadIdx.x;
    if (i < B_ * C_) out[i] = 0.0f;
}

__global__ __launch_bounds__(THREADS)
void offroad_kernel(const float* __restrict__ points,
                    const float* __restrict__ road_boundary,
                    const float* __restrict__ centerlines,
                    float* __restrict__ out) {
    __shared__ float4 sSeg[NSEGP];   // ax, ay, dx, dy
    __shared__ float  sInv[NSEGP];   // 1/(|d|^2+eps)
    __shared__ float2 sClq[NCL];
    __shared__ float  sClh[NCL];     // 0.5*|q|^2
    __shared__ float  sVal[GROUPS];

    const int bid = blockIdx.x;
    const int half = bid & 1;
    const int c = (bid >> 1) % C_;
    const int b = bid / (2 * C_);
    const int tid = threadIdx.x;

    // ---- fill segments (padded) ----
    {
        const float2* rb = (const float2*)road_boundary + (size_t)b * K_ * N_;
        #pragma unroll
        for (int s = tid; s < NSEGP; s += THREADS) {
            float4 v; float inv;
            if (s < NSEG) {
                int k = s / (N_ - 1);
                int j = s - k * (N_ - 1);
                float2 a = rb[k * N_ + j];
                float2 e = rb[k * N_ + j + 1];
                float dx = e.x - a.x, dy = e.y - a.y;
                v = make_float4(a.x, a.y, dx, dy);
                inv = 1.0f / (dx * dx + dy * dy + EPS_);
            } else {
                v = make_float4(1e19f, 1e19f, 0.0f, 0.0f);  // inert dummy
                inv = 0.0f;
            }
            sSeg[s] = v;
            sInv[s] = inv;
        }
    }
    // ---- fill centerlines ----
    {
        const float2* cl = (const float2*)centerlines + (size_t)b * NCL;
        #pragma unroll
        for (int i = tid; i < NCL; i += THREADS) {
            float2 q = cl[i];
            sClq[i] = q;
            sClh[i] = 0.5f * fmaf(q.x, q.x, q.y * q.y);
        }
    }
    __syncthreads();

    const int g = tid >> 4;     // point group (0..7)
    const int l = tid & 15;     // lane within group

    float px[M], py[M];
    #pragma unroll
    for (int j = 0; j < M; j++) {
        int t = half * PTS_BLK + g * M + j;
        float2 p = ((const float2*)points)[((size_t)(b * C_ + c)) * T_ + t];
        px[j] = p.x; py[j] = p.y;
    }

    // ---- Phase A: argmin over centerline candidates (score = 0.5|q|^2 - p.q) ----
    float sc[M]; int bi[M];
    #pragma unroll
    for (int j = 0; j < M; j++) { sc[j] = 3.4e38f; bi[j] = 0; }
    #pragma unroll 4
    for (int it = 0; it < NCL / L; it++) {
        int i = l + it * L;
        float2 q = sClq[i];
        float h = sClh[i];
        #pragma unroll
        for (int j = 0; j < M; j++) {
            float s = fmaf(-px[j], q.x, h);
            s = fmaf(-py[j], q.y, s);
            if (s < sc[j]) { sc[j] = s; bi[j] = i; }
        }
    }
    #pragma unroll
    for (int off = 8; off; off >>= 1) {
        #pragma unroll
        for (int j = 0; j < M; j++) {
            float os = __shfl_xor_sync(0xffffffffu, sc[j], off);
            int   oi = __shfl_xor_sync(0xffffffffu, bi[j], off);
            if (os < sc[j] || (os == sc[j] && oi < bi[j])) { sc[j] = os; bi[j] = oi; }
        }
    }
    float dax[M], day[M];
    #pragma unroll
    for (int j = 0; j < M; j++) {
        float2 q = sClq[bi[j]];       // broadcast (all 16 lanes same idx)
        dax[j] = q.x - px[j];
        day[j] = q.y - py[j];
    }

    // ---- Phase B: fused min-distance + intersection over segments ----
    float mind2[M], hitm[M];
    #pragma unroll
    for (int j = 0; j < M; j++) { mind2[j] = 3.4e38f; hitm[j] = -3.4e38f; }
    #pragma unroll 2
    for (int it = 0; it < NSEGP / L; it++) {
        int s = l + it * L;
        float4 sg = sSeg[s];
        float inv = sInv[s];
        #pragma unroll
        for (int j = 0; j < M; j++) {
            float v1x = px[j] - sg.x;
            float v1y = py[j] - sg.y;
            // point-to-segment distance
            float dt = fmaf(v1y, sg.w, v1x * sg.z);
            float proj = __saturatef(dt * inv);
            float ex = fmaf(sg.z, proj, -v1x);
            float ey = fmaf(sg.w, proj, -v1y);
            float d2 = fmaf(ey, ey, ex * ex);
            mind2[j] = fminf(mind2[j], d2);
            // intersection of (p -> closest_cl) with segment; dp == v1
            float w  = fmaf(dax[j], sg.w, -day[j] * sg.z) + EPS_;   // cross(da,db)+eps
            float c1 = fmaf(dax[j], v1y, -day[j] * v1x);            // cross(da,dp)
            float c2 = fmaf(sg.z,   v1y, -sg.w   * v1x);            // cross(db,dp)
            float aw = fabsf(w);
            // hit iff c1*w>=0 && |c1|<=|w| && c2*w>=0 && |c2|<=|w|
            float m = fminf(fminf(c1 * w, c2 * w),
                            fminf(aw - fabsf(c1), aw - fabsf(c2)));
            hitm[j] = fmaxf(hitm[j], m);
        }
    }
    #pragma unroll
    for (int off = 8; off; off >>= 1) {
        #pragma unroll
        for (int j = 0; j < M; j++) {
            mind2[j] = fminf(mind2[j], __shfl_xor_sync(0xffffffffu, mind2[j], off));
            hitm[j]  = fmaxf(hitm[j],  __shfl_xor_sync(0xffffffffu, hitm[j], off));
        }
    }

    if (l == 0) {
        float acc = 0.0f;
        #pragma unroll
        for (int j = 0; j < M; j++) {
            float md = sqrtf(mind2[j]);
            md = (hitm[j] >= 0.0f) ? md : -md;    // no hit -> inside -> negative
            acc += fmaxf(md + THRESH_, 0.0f);
        }
        sVal[g] = acc;
    }
    __syncthreads();

    if (tid == 0) {
        float ssum = 0.0f;
        #pragma unroll
        for (int i = 0; i < GROUPS; i++) ssum += sVal[i];
        atomicAdd(&out[b * C_ + c], ssum);
    }
}

extern "C" void kernel_launch(void* const* d_in, const int* in_sizes, int n_in,
                              void* d_out, int out_size) {
    const float* points      = (const float*)d_in[0];
    const float* road_bound  = (const float*)d_in[1];
    const float* centerlines = (const float*)d_in[2];
    float* out = (float*)d_out;
    (void)in_sizes; (void)n_in; (void)out_size;

    offroad_init_kernel<<<1, 256>>>(out);
    offroad_kernel<<<B_ * C_ * (T_ / PTS_BLK), THREADS>>>(points, road_bound, centerlines, out);
}

// round 3
// speedup vs baseline: 1.1606x; 1.0012x over previous
#include <cuda_runtime.h>
#include <cuda_bf16.h>
#include <math.h>

// Fixed shapes
#define B_ 32
#define C_ 6
#define T_ 64
#define K_ 8
#define N_ 128
#define NSEG (K_ * (N_ - 1))   // 1016
#define NSEGP 1024             // padded with inert dummies
#define NCL 2048
#define EPS_ 1e-6f
#define THRESH_ 0.5f

#define L 16                   // lanes per point-group
#define M 2                    // points per thread
#define THREADS 256
#define GROUPS (THREADS / L)   // 16
#define PTS_BLK (GROUPS * M)   // 32
#define HALVES (T_ / PTS_BLK)  // 2
// grid = B*C*HALVES = 384

__global__ void offroad_init_kernel(float* out) {
    int i = threadIdx.x;
    if (i < B_ * C_) out[i] = 0.0f;
}

__global__ __launch_bounds__(THREADS)
void offroad_kernel(const float* __restrict__ points,
                    const float* __restrict__ road_boundary,
                    const float* __restrict__ centerlines,
                    float* __restrict__ out) {
    __shared__ float4 sSeg[NSEGP];   // ax, ay, dx, dy
    __shared__ float  sInv[NSEGP];   // 1/(|d|^2+eps)
    __shared__ float4 sCl[NCL];      // qx, qy, 0.5*|q|^2, pad
    __shared__ float  sVal[GROUPS];

    const int bid = blockIdx.x;
    const int half = bid & 1;
    const int c = (bid >> 1) % C_;
    const int b = bid / (2 * C_);
    const int tid = threadIdx.x;

    // ---- fill segments (padded to 1024 with inert dummies) ----
    {
        const float2* rb = (const float2*)road_boundary + (size_t)b * K_ * N_;
        #pragma unroll
        for (int s0 = 0; s0 < NSEGP; s0 += THREADS) {
            int s = s0 + tid;
            float4 v; float inv;
            if (s < NSEG) {
                int k = s / (N_ - 1);
                int j = s - k * (N_ - 1);
                float2 a = rb[k * N_ + j];
                float2 e = rb[k * N_ + j + 1];
                float dx = e.x - a.x, dy = e.y - a.y;
                v = make_float4(a.x, a.y, dx, dy);
                inv = 1.0f / (dx * dx + dy * dy + EPS_);
            } else {
                v = make_float4(1e19f, 1e19f, 0.0f, 0.0f);
                inv = 0.0f;
            }
            sSeg[s] = v;
            sInv[s] = inv;
        }
    }
    // ---- fill centerlines (q, 0.5|q|^2) ----
    {
        const float2* cl = (const float2*)centerlines + (size_t)b * NCL;
        #pragma unroll
        for (int i0 = 0; i0 < NCL; i0 += THREADS) {
            int i = i0 + tid;
            float2 q = cl[i];
            sCl[i] = make_float4(q.x, q.y, 0.5f * fmaf(q.x, q.x, q.y * q.y), 0.0f);
        }
    }
    __syncthreads();

    const int g = tid >> 4;     // point group (0..15)
    const int l = tid & 15;     // lane within group

    float px[M], py[M];
    #pragma unroll
    for (int j = 0; j < M; j++) {
        int t = half * PTS_BLK + g * M + j;
        float2 p = ((const float2*)points)[((size_t)(b * C_ + c)) * T_ + t];
        px[j] = p.x; py[j] = p.y;
    }

    // ---- Phase A: argmin over centerline candidates (score = 0.5|q|^2 - p.q) ----
    float sc[M]; int bi[M];
    #pragma unroll
    for (int j = 0; j < M; j++) { sc[j] = 3.4e38f; bi[j] = 0; }
    #pragma unroll 4
    for (int it = 0; it < NCL / L; it++) {
        int i = l + it * L;
        float4 q = sCl[i];
        #pragma unroll
        for (int j = 0; j < M; j++) {
            float s = fmaf(-py[j], q.y, fmaf(-px[j], q.x, q.z));
            if (s < sc[j]) { sc[j] = s; bi[j] = i; }
        }
    }
    #pragma unroll
    for (int off = 8; off; off >>= 1) {
        #pragma unroll
        for (int j = 0; j < M; j++) {
            float os = __shfl_xor_sync(0xffffffffu, sc[j], off);
            int   oi = __shfl_xor_sync(0xffffffffu, bi[j], off);
            if (os < sc[j] || (os == sc[j] && oi < bi[j])) { sc[j] = os; bi[j] = oi; }
        }
    }
    float dax[M], day[M];
    #pragma unroll
    for (int j = 0; j < M; j++) {
        float4 q = sCl[bi[j]];        // broadcast (all 16 lanes same idx)
        dax[j] = q.x - px[j];
        day[j] = q.y - py[j];
    }

    // ---- Phase B: fused min-distance + intersection over segments ----
    float mind2[M], hitm[M];
    #pragma unroll
    for (int j = 0; j < M; j++) { mind2[j] = 3.4e38f; hitm[j] = -3.4e38f; }
    #pragma unroll 2
    for (int it = 0; it < NSEGP / L; it++) {
        int s = l + it * L;
        float4 sg = sSeg[s];
        float inv = sInv[s];
        #pragma unroll
        for (int j = 0; j < M; j++) {
            float v1x = px[j] - sg.x;
            float v1y = py[j] - sg.y;
            // point-to-segment distance
            float dt = fmaf(v1y, sg.w, v1x * sg.z);
            float proj = __saturatef(dt * inv);
            float ex = fmaf(sg.z, proj, -v1x);
            float ey = fmaf(sg.w, proj, -v1y);
            float d2 = fmaf(ey, ey, ex * ex);
            mind2[j] = fminf(mind2[j], d2);
            // intersection of (p -> closest_cl) with segment; dp == v1
            float w  = fmaf(-day[j], sg.z, fmaf(dax[j], sg.w, EPS_)); // cross(da,db)+eps
            float c1 = fmaf(dax[j], v1y, -day[j] * v1x);              // cross(da,dp)
            float c2 = fmaf(sg.z,   v1y, -sg.w   * v1x);              // cross(db,dp)
            float aw = fabsf(w);
            // hit iff c1*w>=0 && |c1|<=|w| && c2*w>=0 && |c2|<=|w|
            float m = fminf(fminf(c1 * w, c2 * w),
                            fminf(aw - fabsf(c1), aw - fabsf(c2)));
            hitm[j] = fmaxf(hitm[j], m);
        }
    }
    #pragma unroll
    for (int off = 8; off; off >>= 1) {
        #pragma unroll
        for (int j = 0; j < M; j++) {
            mind2[j] = fminf(mind2[j], __shfl_xor_sync(0xffffffffu, mind2[j], off));
            hitm[j]  = fmaxf(hitm[j],  __shfl_xor_sync(0xffffffffu, hitm[j], off));
        }
    }

    if (l == 0) {
        float acc = 0.0f;
        #pragma unroll
        for (int j = 0; j < M; j++) {
            float md = sqrtf(mind2[j]);
            md = (hitm[j] >= 0.0f) ? md : -md;    // no hit -> inside -> negative
            acc += fmaxf(md + THRESH_, 0.0f);
        }
        sVal[g] = acc;
    }
    __syncthreads();

    if (tid == 0) {
        float ssum = 0.0f;
        #pragma unroll
        for (int i = 0; i < GROUPS; i++) ssum += sVal[i];
        atomicAdd(&out[b * C_ + c], ssum);
    }
}

extern "C" void kernel_launch(void* const* d_in, const int* in_sizes, int n_in,
                              void* d_out, int out_size) {
    const float* points      = (const float*)d_in[0];
    const float* road_bound  = (const float*)d_in[1];
    const float* centerlines = (const float*)d_in[2];
    float* out = (float*)d_out;
    (void)in_sizes; (void)n_in; (void)out_size;

    offroad_init_kernel<<<1, 256>>>(out);
    offroad_kernel<<<B_ * C_ * HALVES, THREADS>>>(points, road_bound, centerlines, out);
}

// round 4
// speedup vs baseline: 1.2538x; 1.0804x over previous
#include <cuda_runtime.h>
#include <cuda_bf16.h>
#include <math.h>

// Fixed shapes
#define B_ 32
#define C_ 6
#define T_ 64
#define K_ 8
#define N_ 128
#define NSEG (K_ * (N_ - 1))   // 1016
#define NSEGP 1024             // padded with inert dummies
#define NCL 2048
#define EPS_ 1e-6f
#define THRESH_ 0.5f

#define L 32                   // lanes per point-group = full warp
#define M 4                    // points per thread (2 packed pairs)
#define THREADS 256
#define WARPS (THREADS / 32)   // 8
#define PTS_BLK (WARPS * M)    // 32
#define HALVES (T_ / PTS_BLK)  // 2
// grid = B*C*HALVES = 384

typedef unsigned long long u64;

__device__ __forceinline__ u64 F2ADD(u64 a, u64 b) {
    u64 d; asm("add.rn.f32x2 %0,%1,%2;" : "=l"(d) : "l"(a), "l"(b)); return d;
}
__device__ __forceinline__ u64 F2MUL(u64 a, u64 b) {
    u64 d; asm("mul.rn.f32x2 %0,%1,%2;" : "=l"(d) : "l"(a), "l"(b)); return d;
}
__device__ __forceinline__ u64 F2FMA(u64 a, u64 b, u64 c) {
    u64 d; asm("fma.rn.f32x2 %0,%1,%2,%3;" : "=l"(d) : "l"(a), "l"(b), "l"(c)); return d;
}
__device__ __forceinline__ u64 F2PK(float lo, float hi) {
    u64 d; asm("mov.b64 %0,{%1,%2};" : "=l"(d) : "f"(lo), "f"(hi)); return d;
}
__device__ __forceinline__ void F2UP(u64 a, float& lo, float& hi) {
    asm("mov.b64 {%0,%1},%2;" : "=f"(lo), "=f"(hi) : "l"(a));
}

__global__ void offroad_init_kernel(float* out) {
    int i = threadIdx.x;
    if (i < B_ * C_) out[i] = 0.0f;
}

__global__ __launch_bounds__(THREADS, 3)
void offroad_kernel(const float* __restrict__ points,
                    const float* __restrict__ road_boundary,
                    const float* __restrict__ centerlines,
                    float* __restrict__ out) {
    // Duplicated (packed-pair) segment layout: each float4 yields two f32x2 operands.
    __shared__ float4 sSegA[NSEGP];   // (-ax,-ax,-ay,-ay)
    __shared__ float4 sSegD[NSEGP];   // (-dx,-dx,-dy,-dy)
    __shared__ float4 sSegM[NSEGP];   // (-inv,-inv, dx, dx)
    __shared__ float2 sClq[NCL];      // (qx,qy)
    __shared__ float  sClh[NCL];      // 0.5*|q|^2
    __shared__ float  sVal[WARPS];

    const int bid = blockIdx.x;
    const int half = bid & 1;
    const int c = (bid >> 1) % C_;
    const int b = bid / (2 * C_);
    const int tid = threadIdx.x;

    // ---- fill segments (padded) ----
    {
        const float2* rb = (const float2*)road_boundary + (size_t)b * K_ * N_;
        #pragma unroll
        for (int s0 = 0; s0 < NSEGP; s0 += THREADS) {
            int s = s0 + tid;
            if (s < NSEG) {
                int k = s / (N_ - 1);
                int j = s - k * (N_ - 1);
                float2 a = rb[k * N_ + j];
                float2 e = rb[k * N_ + j + 1];
                float dx = e.x - a.x, dy = e.y - a.y;
                float inv = 1.0f / (dx * dx + dy * dy + EPS_);
                sSegA[s] = make_float4(-a.x, -a.x, -a.y, -a.y);
                sSegD[s] = make_float4(-dx, -dx, -dy, -dy);
                sSegM[s] = make_float4(-inv, -inv, dx, dx);
            } else {
                sSegA[s] = make_float4(-1e19f, -1e19f, -1e19f, -1e19f);
                sSegD[s] = make_float4(0.f, 0.f, 0.f, 0.f);
                sSegM[s] = make_float4(0.f, 0.f, 0.f, 0.f);
            }
        }
    }
    // ---- fill centerlines ----
    {
        const float2* cl = (const float2*)centerlines + (size_t)b * NCL;
        #pragma unroll
        for (int i0 = 0; i0 < NCL; i0 += THREADS) {
            int i = i0 + tid;
            float2 q = cl[i];
            sClq[i] = q;
            sClh[i] = 0.5f * fmaf(q.x, q.x, q.y * q.y);
        }
    }
    __syncthreads();

    const int w = tid >> 5;     // warp = point group (0..7)
    const int l = tid & 31;     // lane

    float px[M], py[M];
    #pragma unroll
    for (int j = 0; j < M; j++) {
        int t = half * PTS_BLK + w * M + j;
        float2 p = ((const float2*)points)[((size_t)(b * C_ + c)) * T_ + t];
        px[j] = p.x; py[j] = p.y;
    }

    // ---- Phase A: argmin over centerline candidates (score = 0.5|q|^2 - p.q) ----
    float sc[M]; int bi[M];
    #pragma unroll
    for (int j = 0; j < M; j++) { sc[j] = 3.4e38f; bi[j] = 0; }
    #pragma unroll 4
    for (int it = 0; it < NCL / L; it++) {
        int i = l + it * L;
        float2 q = sClq[i];
        float h = sClh[i];
        #pragma unroll
        for (int j = 0; j < M; j++) {
            float s = fmaf(-py[j], q.y, fmaf(-px[j], q.x, h));
            if (s < sc[j]) { sc[j] = s; bi[j] = i; }
        }
    }
    #pragma unroll
    for (int off = 16; off; off >>= 1) {
        #pragma unroll
        for (int j = 0; j < M; j++) {
            float os = __shfl_xor_sync(0xffffffffu, sc[j], off);
            int   oi = __shfl_xor_sync(0xffffffffu, bi[j], off);
            if (os < sc[j] || (os == sc[j] && oi < bi[j])) { sc[j] = os; bi[j] = oi; }
        }
    }

    // Per-pair packed constants for phase B
    u64 px2[M/2], py2[M/2], dax2[M/2], ndax2[M/2], day2[M/2], nday2[M/2];
    #pragma unroll
    for (int q_ = 0; q_ < M / 2; q_++) {
        int j0 = 2 * q_, j1 = 2 * q_ + 1;
        float2 q0 = sClq[bi[j0]];      // broadcast reads
        float2 q1 = sClq[bi[j1]];
        float dax0 = q0.x - px[j0], day0 = q0.y - py[j0];
        float dax1 = q1.x - px[j1], day1 = q1.y - py[j1];
        px2[q_]   = F2PK(px[j0], px[j1]);
        py2[q_]   = F2PK(py[j0], py[j1]);
        dax2[q_]  = F2PK(dax0, dax1);
        ndax2[q_] = F2PK(-dax0, -dax1);
        day2[q_]  = F2PK(day0, day1);
        nday2[q_] = F2PK(-day0, -day1);
    }
    const u64 eps2 = F2PK(EPS_, EPS_);

    // ---- Phase B: fused min-distance + intersection over segments (packed f32x2) ----
    float mind2[M], hitm[M];
    #pragma unroll
    for (int j = 0; j < M; j++) { mind2[j] = 3.4e38f; hitm[j] = -3.4e38f; }

    const ulonglong2* segA = (const ulonglong2*)sSegA;
    const ulonglong2* segD = (const ulonglong2*)sSegD;
    const ulonglong2* segM = (const ulonglong2*)sSegM;

    #pragma unroll 2
    for (int it = 0; it < NSEGP / L; it++) {
        int s = l + it * L;
        ulonglong2 va = segA[s];   // va.x = (-ax,-ax), va.y = (-ay,-ay)
        ulonglong2 vd = segD[s];   // vd.x = (-dx,-dx), vd.y = (-dy,-dy)
        ulonglong2 vm = segM[s];   // vm.x = (-inv,-inv), vm.y = (dx,dx)
        #pragma unroll
        for (int q_ = 0; q_ < M / 2; q_++) {
            u64 v1x = F2ADD(px2[q_], va.x);                 // p - a
            u64 v1y = F2ADD(py2[q_], va.y);
            u64 dtn = F2FMA(v1y, vd.y, F2MUL(v1x, vd.x));   // -(v1.d)
            u64 pr  = F2MUL(dtn, vm.x);                     // dt*inv
            float p0, p1; F2UP(pr, p0, p1);
            p0 = __saturatef(p0); p1 = __saturatef(p1);
            pr = F2PK(p0, p1);
            u64 ex = F2FMA(vd.x, pr, v1x);                  // v1x - dx*pr
            u64 ey = F2FMA(vd.y, pr, v1y);
            u64 d2 = F2FMA(ey, ey, F2MUL(ex, ex));
            float d20, d21; F2UP(d2, d20, d21);
            mind2[2*q_]   = fminf(mind2[2*q_],   d20);
            mind2[2*q_+1] = fminf(mind2[2*q_+1], d21);
            // w = dax*dy - day*dx + eps = ndax*ndy + day*ndx + eps
            u64 wv = F2FMA(day2[q_], vd.x, F2FMA(ndax2[q_], vd.y, eps2));
            // c1 = dax*v1y - day*v1x
            u64 c1 = F2FMA(dax2[q_], v1y, F2MUL(nday2[q_], v1x));
            // c2 = dx*v1y - dy*v1x = dx*v1y + ndy*v1x
            u64 c2 = F2FMA(vm.y, v1y, F2MUL(vd.y, v1x));
            u64 c1w = F2MUL(c1, wv);
            u64 c2w = F2MUL(c2, wv);
            float w0, w1, a0, a1, b0, b1, e0, e1, f0, f1;
            F2UP(wv, w0, w1); F2UP(c1, a0, a1); F2UP(c2, b0, b1);
            F2UP(c1w, e0, e1); F2UP(c2w, f0, f1);
            float m0 = fminf(fminf(e0, f0),
                             fminf(fabsf(w0) - fabsf(a0), fabsf(w0) - fabsf(b0)));
            float m1 = fminf(fminf(e1, f1),
                             fminf(fabsf(w1) - fabsf(a1), fabsf(w1) - fabsf(b1)));
            hitm[2*q_]   = fmaxf(hitm[2*q_],   m0);
            hitm[2*q_+1] = fmaxf(hitm[2*q_+1], m1);
        }
    }
    #pragma unroll
    for (int off = 16; off; off >>= 1) {
        #pragma unroll
        for (int j = 0; j < M; j++) {
            mind2[j] = fminf(mind2[j], __shfl_xor_sync(0xffffffffu, mind2[j], off));
            hitm[j]  = fmaxf(hitm[j],  __shfl_xor_sync(0xffffffffu, hitm[j], off));
        }
    }

    if (l == 0) {
        float acc = 0.0f;
        #pragma unroll
        for (int j = 0; j < M; j++) {
            float md = sqrtf(mind2[j]);
            md = (hitm[j] >= 0.0f) ? md : -md;    // no hit -> inside -> negative
            acc += fmaxf(md + THRESH_, 0.0f);
        }
        sVal[w] = acc;
    }
    __syncthreads();

    if (tid == 0) {
        float ssum = 0.0f;
        #pragma unroll
        for (int i = 0; i < WARPS; i++) ssum += sVal[i];
        atomicAdd(&out[b * C_ + c], ssum);
    }
}

extern "C" void kernel_launch(void* const* d_in, const int* in_sizes, int n_in,
                              void* d_out, int out_size) {
    const float* points      = (const float*)d_in[0];
    const float* road_bound  = (const float*)d_in[1];
    const float* centerlines = (const float*)d_in[2];
    float* out = (float*)d_out;
    (void)in_sizes; (void)n_in; (void)out_size;

    offroad_init_kernel<<<1, 256>>>(out);
    offroad_kernel<<<B_ * C_ * HALVES, THREADS>>>(points, road_bound, centerlines, out);
}